// round 1
// baseline (speedup 1.0000x reference)
#include <cuda_runtime.h>

#define NODES 50000
#define NE    800000
#define HID   128
#define NPART 32
#define BN_EPS 1e-5f

// ---------------- scratch (device globals; no runtime alloc) ----------------
__device__ float g_deg[NODES];
__device__ int   g_cnt[NODES];
__device__ int   g_off[NODES + 1];
__device__ int   g_cur[NODES];
__device__ float g_dinv[NODES];
__device__ int   g_csr_src[NE];
__device__ float g_csr_norm[NE];
__device__ float g_hw[NODES * HID];
__device__ float g_agg[NODES * HID];
__device__ float g_stats[2 * HID];
__device__ float g_mean[HID];
__device__ float g_scale[HID];
__device__ float g_base[HID];
__device__ float g_we[HID];

// ---------------- init ----------------
__global__ void zero_init_kernel(float* out) {
    int i = blockIdx.x * blockDim.x + threadIdx.x;
    if (i < NODES) { g_deg[i] = 0.f; g_cnt[i] = 0; g_cur[i] = 0; }
    if (i < NPART) out[i] = 0.f;
}

__global__ void zero_stats_kernel() {
    g_stats[threadIdx.x] = 0.f;   // 256 threads
}

// ---------------- degree + count ----------------
__global__ void deg_count_kernel(const int* __restrict__ ei,
                                 const float* __restrict__ ew) {
    int e = blockIdx.x * blockDim.x + threadIdx.x;
    if (e >= NE) return;
    int dst = ei[NE + e];
    atomicAdd(&g_deg[dst], ew[e]);
    atomicAdd(&g_cnt[dst], 1);
}

__global__ void dinv_kernel() {
    int n = blockIdx.x * blockDim.x + threadIdx.x;
    if (n < NODES) g_dinv[n] = rsqrtf(g_deg[n] + 1.0f);
}

// ---------------- exclusive scan of counts (1 block, 1024 threads) ----------------
__global__ void scan_kernel() {
    __shared__ int wsum[32];
    __shared__ int s_carry;
    int t = threadIdx.x, lane = t & 31, warp = t >> 5;
    if (t == 0) s_carry = 0;
    __syncthreads();
    for (int base = 0; base < NODES; base += 1024) {
        int idx = base + t;
        int v = (idx < NODES) ? g_cnt[idx] : 0;
        int inc = v;
        #pragma unroll
        for (int o = 1; o < 32; o <<= 1) {
            int u = __shfl_up_sync(0xffffffffu, inc, o);
            if (lane >= o) inc += u;
        }
        if (lane == 31) wsum[warp] = inc;
        __syncthreads();
        if (warp == 0) {
            int wv = wsum[lane];
            int winc = wv;
            #pragma unroll
            for (int o = 1; o < 32; o <<= 1) {
                int u = __shfl_up_sync(0xffffffffu, winc, o);
                if (lane >= o) winc += u;
            }
            wsum[lane] = winc - wv;   // exclusive warp offsets
        }
        __syncthreads();
        if (idx < NODES) g_off[idx] = s_carry + wsum[warp] + inc - v;
        __syncthreads();
        if (t == 1023) s_carry += wsum[31] + inc;
        __syncthreads();
    }
    if (threadIdx.x == 0) g_off[NODES] = s_carry;
}

// ---------------- CSR fill ----------------
__global__ void csr_fill_kernel(const int* __restrict__ ei,
                                const float* __restrict__ ew) {
    int e = blockIdx.x * blockDim.x + threadIdx.x;
    if (e >= NE) return;
    int src = ei[e];
    int dst = ei[NE + e];
    int pos = g_off[dst] + atomicAdd(&g_cur[dst], 1);
    g_csr_src[pos]  = src;
    g_csr_norm[pos] = g_dinv[src] * ew[e] * g_dinv[dst];
}

// ---------------- GEMM: g_hw = A[nrows,128] @ W[128,128] + bias ----------------
__global__ __launch_bounds__(256) void gemm_kernel(
    const float* __restrict__ A, const float* __restrict__ W,
    const float* __restrict__ bias, int nrows)
{
    __shared__ float As[32 * 132];   // [k][row], padded
    __shared__ float Bs[32 * 128];   // [k][col]
    int tid = threadIdx.x;
    int tr = tid >> 4, tc = tid & 15;
    int row0 = blockIdx.x * 128;
    float acc[8][8];
    #pragma unroll
    for (int i = 0; i < 8; i++)
        #pragma unroll
        for (int j = 0; j < 8; j++) acc[i][j] = 0.f;

    for (int kc = 0; kc < HID; kc += 32) {
        #pragma unroll
        for (int i = 0; i < 4; i++) {
            int slot = tid + i * 256;
            int r  = slot >> 3;
            int k4 = slot & 7;
            float4 v = make_float4(0.f, 0.f, 0.f, 0.f);
            if (row0 + r < nrows)
                v = *(const float4*)(A + (size_t)(row0 + r) * HID + kc + k4 * 4);
            As[(k4 * 4 + 0) * 132 + r] = v.x;
            As[(k4 * 4 + 1) * 132 + r] = v.y;
            As[(k4 * 4 + 2) * 132 + r] = v.z;
            As[(k4 * 4 + 3) * 132 + r] = v.w;
        }
        #pragma unroll
        for (int i = 0; i < 4; i++) {
            int slot = tid + i * 256;
            int k  = slot >> 5;
            int c4 = slot & 31;
            *(float4*)(Bs + k * 128 + c4 * 4) =
                *(const float4*)(W + (size_t)(kc + k) * HID + c4 * 4);
        }
        __syncthreads();
        #pragma unroll
        for (int k = 0; k < 32; k++) {
            float4 a0 = *(float4*)(As + k * 132 + tr * 8);
            float4 a1 = *(float4*)(As + k * 132 + tr * 8 + 4);
            float4 b0 = *(float4*)(Bs + k * 128 + tc * 8);
            float4 b1 = *(float4*)(Bs + k * 128 + tc * 8 + 4);
            float a[8] = {a0.x, a0.y, a0.z, a0.w, a1.x, a1.y, a1.z, a1.w};
            float b[8] = {b0.x, b0.y, b0.z, b0.w, b1.x, b1.y, b1.z, b1.w};
            #pragma unroll
            for (int i = 0; i < 8; i++)
                #pragma unroll
                for (int j = 0; j < 8; j++)
                    acc[i][j] += a[i] * b[j];
        }
        __syncthreads();
    }
    float bv[8];
    #pragma unroll
    for (int j = 0; j < 8; j++) bv[j] = bias[tc * 8 + j];
    #pragma unroll
    for (int i = 0; i < 8; i++) {
        int row = row0 + tr * 8 + i;
        if (row < nrows) {
            float4 o0 = make_float4(acc[i][0] + bv[0], acc[i][1] + bv[1],
                                    acc[i][2] + bv[2], acc[i][3] + bv[3]);
            float4 o1 = make_float4(acc[i][4] + bv[4], acc[i][5] + bv[5],
                                    acc[i][6] + bv[6], acc[i][7] + bv[7]);
            *(float4*)(g_hw + (size_t)row * HID + tc * 8)     = o0;
            *(float4*)(g_hw + (size_t)row * HID + tc * 8 + 4) = o1;
        }
    }
}

// ---------------- aggregation (warp per node) + BN stats ----------------
__global__ __launch_bounds__(256) void agg_kernel() {
    __shared__ float bsum[HID];
    __shared__ float bss[HID];
    int tid = threadIdx.x;
    for (int i = tid; i < HID; i += blockDim.x) { bsum[i] = 0.f; bss[i] = 0.f; }
    __syncthreads();

    int lane = tid & 31;
    int wglobal = (blockIdx.x * blockDim.x + tid) >> 5;
    int nwarps  = (gridDim.x * blockDim.x) >> 5;

    float ls0 = 0.f, ls1 = 0.f, ls2 = 0.f, ls3 = 0.f;
    float lq0 = 0.f, lq1 = 0.f, lq2 = 0.f, lq3 = 0.f;

    for (int n = wglobal; n < NODES; n += nwarps) {
        float dv = g_dinv[n];
        float sn = dv * dv;
        float4 a = ((const float4*)(g_hw + (size_t)n * HID))[lane];
        float4 acc = make_float4(a.x * sn, a.y * sn, a.z * sn, a.w * sn);
        int beg = g_off[n], end = g_off[n + 1];
        for (int i = beg; i < end; i++) {
            int s  = g_csr_src[i];
            float w = g_csr_norm[i];
            float4 v = ((const float4*)(g_hw + (size_t)s * HID))[lane];
            acc.x += w * v.x; acc.y += w * v.y;
            acc.z += w * v.z; acc.w += w * v.w;
        }
        ((float4*)(g_agg + (size_t)n * HID))[lane] = acc;
        ls0 += acc.x; ls1 += acc.y; ls2 += acc.z; ls3 += acc.w;
        lq0 += acc.x * acc.x; lq1 += acc.y * acc.y;
        lq2 += acc.z * acc.z; lq3 += acc.w * acc.w;
    }
    int c = lane * 4;
    atomicAdd(&bsum[c + 0], ls0); atomicAdd(&bsum[c + 1], ls1);
    atomicAdd(&bsum[c + 2], ls2); atomicAdd(&bsum[c + 3], ls3);
    atomicAdd(&bss[c + 0], lq0);  atomicAdd(&bss[c + 1], lq1);
    atomicAdd(&bss[c + 2], lq2);  atomicAdd(&bss[c + 3], lq3);
    __syncthreads();
    for (int i = tid; i < HID; i += blockDim.x) {
        atomicAdd(&g_stats[i],       bsum[i]);
        atomicAdd(&g_stats[HID + i], bss[i]);
    }
}

__global__ void finalize_stats_kernel() {
    int j = threadIdx.x;   // 128
    float m = g_stats[j] * (1.0f / NODES);
    float v = g_stats[HID + j] * (1.0f / NODES) - m * m;
    g_mean[j]  = m;
    g_scale[j] = rsqrtf(v + BN_EPS);
}

__global__ void bn_relu_kernel(float* __restrict__ h) {
    int idx = blockIdx.x * blockDim.x + threadIdx.x;   // float4 index
    if (idx >= NODES * 32) return;
    int c = (idx & 31) * 4;
    float4 v = ((const float4*)g_agg)[idx];
    float4 r;
    r.x = fmaxf((v.x - g_mean[c + 0]) * g_scale[c + 0], 0.f);
    r.y = fmaxf((v.y - g_mean[c + 1]) * g_scale[c + 1], 0.f);
    r.z = fmaxf((v.z - g_mean[c + 2]) * g_scale[c + 2], 0.f);
    r.w = fmaxf((v.w - g_mean[c + 3]) * g_scale[c + 3], 0.f);
    ((float4*)h)[idx] = r;
}

// ---------------- scoring prep: base[j] = b1[j] + xcurr@W1[128:256]; we[j] = sum W1[256:512] ----------------
__global__ void prep_kernel(const float* __restrict__ h,
                            const float* __restrict__ l1w,
                            const float* __restrict__ l1b,
                            const int* __restrict__ curr) {
    int j = threadIdx.x;   // 128
    int c = *curr;
    float acc = 0.f;
    #pragma unroll 8
    for (int k = 0; k < HID; k++)
        acc += h[(size_t)c * HID + k] * l1w[(size_t)(HID + k) * HID + j];
    g_base[j] = l1b[j] + acc;
    float we = 0.f;
    #pragma unroll 8
    for (int k = 2 * HID; k < 4 * HID; k++)
        we += l1w[(size_t)k * HID + j];
    g_we[j] = we;
}

// ---------------- scoring GEMM + relu.w2 dot + partition pooling ----------------
__global__ __launch_bounds__(256) void score_kernel(
    const float* __restrict__ A,    // h
    const float* __restrict__ W,    // lin1_w rows 0..127
    const float* __restrict__ l2w, const float* __restrict__ l2b,
    const float* __restrict__ ecn, const float* __restrict__ parts,
    float* __restrict__ out)
{
    __shared__ float As[32 * 132];
    __shared__ float Bs[32 * 128];
    __shared__ float sarr[128];
    __shared__ float pp[NPART];
    int tid = threadIdx.x;
    int tr = tid >> 4, tc = tid & 15;
    int row0 = blockIdx.x * 128;
    float acc[8][8];
    #pragma unroll
    for (int i = 0; i < 8; i++)
        #pragma unroll
        for (int j = 0; j < 8; j++) acc[i][j] = 0.f;

    for (int kc = 0; kc < HID; kc += 32) {
        #pragma unroll
        for (int i = 0; i < 4; i++) {
            int slot = tid + i * 256;
            int r  = slot >> 3;
            int k4 = slot & 7;
            float4 v = make_float4(0.f, 0.f, 0.f, 0.f);
            if (row0 + r < NODES)
                v = *(const float4*)(A + (size_t)(row0 + r) * HID + kc + k4 * 4);
            As[(k4 * 4 + 0) * 132 + r] = v.x;
            As[(k4 * 4 + 1) * 132 + r] = v.y;
            As[(k4 * 4 + 2) * 132 + r] = v.z;
            As[(k4 * 4 + 3) * 132 + r] = v.w;
        }
        #pragma unroll
        for (int i = 0; i < 4; i++) {
            int slot = tid + i * 256;
            int k  = slot >> 5;
            int c4 = slot & 31;
            *(float4*)(Bs + k * 128 + c4 * 4) =
                *(const float4*)(W + (size_t)(kc + k) * HID + c4 * 4);
        }
        __syncthreads();
        #pragma unroll
        for (int k = 0; k < 32; k++) {
            float4 a0 = *(float4*)(As + k * 132 + tr * 8);
            float4 a1 = *(float4*)(As + k * 132 + tr * 8 + 4);
            float4 b0 = *(float4*)(Bs + k * 128 + tc * 8);
            float4 b1 = *(float4*)(Bs + k * 128 + tc * 8 + 4);
            float a[8] = {a0.x, a0.y, a0.z, a0.w, a1.x, a1.y, a1.z, a1.w};
            float b[8] = {b0.x, b0.y, b0.z, b0.w, b1.x, b1.y, b1.z, b1.w};
            #pragma unroll
            for (int i = 0; i < 8; i++)
                #pragma unroll
                for (int j = 0; j < 8; j++)
                    acc[i][j] += a[i] * b[j];
        }
        __syncthreads();
    }

    float w2[8], bb[8], wev[8];
    #pragma unroll
    for (int j = 0; j < 8; j++) {
        w2[j]  = l2w[tc * 8 + j];
        bb[j]  = g_base[tc * 8 + j];
        wev[j] = g_we[tc * 8 + j];
    }
    float b2 = l2b[0];
    #pragma unroll
    for (int i = 0; i < 8; i++) {
        int row = row0 + tr * 8 + i;
        float e = (row < NODES) ? ecn[row] : 0.f;
        float s = 0.f;
        #pragma unroll
        for (int j = 0; j < 8; j++) {
            float t = acc[i][j] + bb[j] + e * wev[j];
            s += fmaxf(t, 0.f) * w2[j];
        }
        s += __shfl_xor_sync(0xffffffffu, s, 8, 16);
        s += __shfl_xor_sync(0xffffffffu, s, 4, 16);
        s += __shfl_xor_sync(0xffffffffu, s, 2, 16);
        s += __shfl_xor_sync(0xffffffffu, s, 1, 16);
        if (tc == 0) sarr[tr * 8 + i] = (row < NODES) ? (s + b2) : 0.f;
    }
    if (tid < NPART) pp[tid] = 0.f;
    __syncthreads();
    int p = tid & 31, g = tid >> 5;
    float psum = 0.f;
    for (int r = g * 16; r < g * 16 + 16; r++) {
        int row = row0 + r;
        if (row < NODES) psum += sarr[r] * parts[(size_t)row * NPART + p];
    }
    atomicAdd(&pp[p], psum);
    __syncthreads();
    if (tid < NPART) atomicAdd(&out[tid], pp[tid]);
}

// ---------------- launcher ----------------
extern "C" void kernel_launch(void* const* d_in, const int* in_sizes, int n_in,
                              void* d_out, int out_size) {
    const float* x      = (const float*)d_in[0];
    const int*   ei     = (const int*)d_in[1];
    const float* ew     = (const float*)d_in[2];
    const float* parts  = (const float*)d_in[3];
    // d_in[4] = node_weights (unused by reference)
    const float* ecn    = (const float*)d_in[5];
    const float* conv_w = (const float*)d_in[6];
    const float* conv_b = (const float*)d_in[7];
    const float* l1w    = (const float*)d_in[8];
    const float* l1b    = (const float*)d_in[9];
    const float* l2w    = (const float*)d_in[10];
    const float* l2b    = (const float*)d_in[11];
    const int*   curr   = (const int*)d_in[12];

    float* out = (float*)d_out;          // [0:32) partition scores
    float* h   = out + NPART;            // [32 : 32+N*H) final h (also layer buffer)

    zero_init_kernel<<<(NODES + 255) / 256, 256>>>(out);
    deg_count_kernel<<<(NE + 255) / 256, 256>>>(ei, ew);
    dinv_kernel<<<(NODES + 255) / 256, 256>>>();
    scan_kernel<<<1, 1024>>>();
    csr_fill_kernel<<<(NE + 255) / 256, 256>>>(ei, ew);

    const int gemm_blocks = (NODES + 127) / 128;   // 391
    const float* hin = x;
    for (int l = 0; l < 3; l++) {
        gemm_kernel<<<gemm_blocks, 256>>>(hin, conv_w + l * HID * HID,
                                          conv_b + l * HID, NODES);
        zero_stats_kernel<<<1, 256>>>();
        agg_kernel<<<1184, 256>>>();
        finalize_stats_kernel<<<1, 128>>>();
        bn_relu_kernel<<<(NODES * 32 + 255) / 256, 256>>>(h);
        hin = h;
    }

    prep_kernel<<<1, 128>>>(h, l1w, l1b, curr);
    score_kernel<<<gemm_blocks, 256>>>(h, l1w, l2w, l2b, ecn, parts, out);
}

// round 3
// speedup vs baseline: 1.1669x; 1.1669x over previous
#include <cuda_runtime.h>

#define NODES 50000
#define NE    800000
#define HID   128
#define NPART 32
#define BN_EPS 1e-5f
#define SBLK  512
#define NSB   ((NODES + SBLK - 1) / SBLK)   // 98

// ---------------- scratch (device globals; no runtime alloc) ----------------
__device__ float g_deg[NODES];
__device__ int   g_cnt[NODES];
__device__ int   g_off[NODES + 1];
__device__ int   g_cur[NODES];
__device__ float g_dinv[NODES];
__device__ int   g_bsum[NSB];
__device__ int   g_boff[NSB];
__device__ int   g_csr_src[NE];
__device__ float g_csr_norm[NE];
__device__ float g_hw[NODES * HID];
__device__ float g_agg[NODES * HID];
__device__ float g_stats[2 * HID];
__device__ float g_mean[HID];
__device__ float g_scale[HID];
__device__ float g_base[HID];
__device__ float g_we[HID];

// ---------------- f32x2 helpers ----------------
__device__ __forceinline__ unsigned long long pk2(float lo, float hi) {
    unsigned long long r;
    asm("mov.b64 %0, {%1, %2};" : "=l"(r) : "f"(lo), "f"(hi));
    return r;
}
__device__ __forceinline__ void fma2(unsigned long long& d,
                                     unsigned long long a,
                                     unsigned long long b) {
    asm("fma.rn.f32x2 %0, %1, %2, %0;" : "+l"(d) : "l"(a), "l"(b));
}
__device__ __forceinline__ float2 upk2(unsigned long long v) {
    float2 f;
    asm("mov.b64 {%0, %1}, %2;" : "=f"(f.x), "=f"(f.y) : "l"(v));
    return f;
}

// ---------------- init ----------------
__global__ void zero_init_kernel(float* out) {
    int i = blockIdx.x * blockDim.x + threadIdx.x;
    if (i < NODES) { g_deg[i] = 0.f; g_cnt[i] = 0; g_cur[i] = 0; }
    if (i < NPART) out[i] = 0.f;
    if (i < 2 * HID) g_stats[i] = 0.f;
}

// ---------------- degree + count ----------------
__global__ void deg_count_kernel(const int* __restrict__ ei,
                                 const float* __restrict__ ew) {
    int e = blockIdx.x * blockDim.x + threadIdx.x;
    if (e >= NE) return;
    int dst = ei[NE + e];
    atomicAdd(&g_deg[dst], ew[e]);
    atomicAdd(&g_cnt[dst], 1);
}

// ---------------- scan stage 1: per-block sums (+ dinv fused) ----------------
__global__ __launch_bounds__(SBLK) void block_sum_kernel() {
    __shared__ int ws[SBLK / 32];
    int t = threadIdx.x, lane = t & 31, w = t >> 5;
    int i = blockIdx.x * SBLK + t;
    int v = (i < NODES) ? g_cnt[i] : 0;
    if (i < NODES) g_dinv[i] = rsqrtf(g_deg[i] + 1.0f);
    int s = v;
    #pragma unroll
    for (int o = 16; o; o >>= 1) s += __shfl_down_sync(0xffffffffu, s, o);
    if (lane == 0) ws[w] = s;
    __syncthreads();
    if (t < SBLK / 32) {
        int x = ws[t];
        #pragma unroll
        for (int o = 8; o; o >>= 1) x += __shfl_down_sync(0x0000ffffu, x, o);
        if (t == 0) g_bsum[blockIdx.x] = x;
    }
}

// ---------------- scan stage 2: scan 98 block sums (1 block, 128 thr) ----------------
__global__ void scan_bsum_kernel() {
    __shared__ int ws[4];
    int t = threadIdx.x, lane = t & 31, w = t >> 5;
    int v = (t < NSB) ? g_bsum[t] : 0;
    int inc = v;
    #pragma unroll
    for (int o = 1; o < 32; o <<= 1) {
        int u = __shfl_up_sync(0xffffffffu, inc, o);
        if (lane >= o) inc += u;
    }
    if (lane == 31) ws[w] = inc;
    __syncthreads();
    int add = 0;
    for (int k = 0; k < w; k++) add += ws[k];
    if (t < NSB) g_boff[t] = add + inc - v;
    if (t == NSB - 1) g_off[NODES] = add + inc;
}

// ---------------- scan stage 3: local scan + offset ----------------
__global__ __launch_bounds__(SBLK) void scan_local_kernel() {
    __shared__ int ws[SBLK / 32];
    int t = threadIdx.x, lane = t & 31, w = t >> 5;
    int i = blockIdx.x * SBLK + t;
    int v = (i < NODES) ? g_cnt[i] : 0;
    int inc = v;
    #pragma unroll
    for (int o = 1; o < 32; o <<= 1) {
        int u = __shfl_up_sync(0xffffffffu, inc, o);
        if (lane >= o) inc += u;
    }
    if (lane == 31) ws[w] = inc;
    __syncthreads();
    int add = g_boff[blockIdx.x];
    for (int k = 0; k < w; k++) add += ws[k];
    if (i < NODES) g_off[i] = add + inc - v;
}

// ---------------- CSR fill ----------------
__global__ void csr_fill_kernel(const int* __restrict__ ei,
                                const float* __restrict__ ew) {
    int e = blockIdx.x * blockDim.x + threadIdx.x;
    if (e >= NE) return;
    int src = ei[e];
    int dst = ei[NE + e];
    int pos = g_off[dst] + atomicAdd(&g_cur[dst], 1);
    g_csr_src[pos]  = src;
    g_csr_norm[pos] = g_dinv[src] * ew[e] * g_dinv[dst];
}

// ---------------- GEMM: g_hw = act(A)[nrows,128] @ W[128,128] + bias ----------------
// use_bn == 0: read from A (harness pointer), no activation on load.
// use_bn == 1: read from g_agg (device global, resolved IN DEVICE CODE) and
//              apply relu((a - g_mean[c]) * g_scale[c]) while staging to smem.
__global__ __launch_bounds__(256) void gemm_kernel(
    const float* __restrict__ A, const float* __restrict__ W,
    const float* __restrict__ bias, int use_bn, int nrows)
{
    __shared__ float As[32 * 132];   // [k][row], padded
    __shared__ float Bs[32 * 128];   // [k][col]
    const float* __restrict__ src = use_bn ? (const float*)g_agg : A;
    int tid = threadIdx.x;
    int tr = tid >> 4, tc = tid & 15;
    int row0 = blockIdx.x * 128;
    unsigned long long acc[4][8];    // row-pairs x 8 cols
    #pragma unroll
    for (int i = 0; i < 4; i++)
        #pragma unroll
        for (int j = 0; j < 8; j++) acc[i][j] = 0ull;

    for (int kc = 0; kc < HID; kc += 32) {
        #pragma unroll
        for (int i = 0; i < 4; i++) {
            int slot = tid + i * 256;
            int r  = slot >> 3;
            int k4 = slot & 7;
            float4 v = make_float4(0.f, 0.f, 0.f, 0.f);
            if (row0 + r < nrows)
                v = *(const float4*)(src + (size_t)(row0 + r) * HID + kc + k4 * 4);
            if (use_bn) {
                int c = kc + k4 * 4;
                v.x = fmaxf((v.x - g_mean[c + 0]) * g_scale[c + 0], 0.f);
                v.y = fmaxf((v.y - g_mean[c + 1]) * g_scale[c + 1], 0.f);
                v.z = fmaxf((v.z - g_mean[c + 2]) * g_scale[c + 2], 0.f);
                v.w = fmaxf((v.w - g_mean[c + 3]) * g_scale[c + 3], 0.f);
            }
            As[(k4 * 4 + 0) * 132 + r] = v.x;
            As[(k4 * 4 + 1) * 132 + r] = v.y;
            As[(k4 * 4 + 2) * 132 + r] = v.z;
            As[(k4 * 4 + 3) * 132 + r] = v.w;
        }
        #pragma unroll
        for (int i = 0; i < 4; i++) {
            int slot = tid + i * 256;
            int k  = slot >> 5;
            int c4 = slot & 31;
            *(float4*)(Bs + k * 128 + c4 * 4) =
                *(const float4*)(W + (size_t)(kc + k) * HID + c4 * 4);
        }
        __syncthreads();
        #pragma unroll
        for (int k = 0; k < 32; k++) {
            float4 a0 = *(float4*)(As + k * 132 + tr * 8);
            float4 a1 = *(float4*)(As + k * 132 + tr * 8 + 4);
            float4 b0 = *(float4*)(Bs + k * 128 + tc * 8);
            float4 b1 = *(float4*)(Bs + k * 128 + tc * 8 + 4);
            unsigned long long ap[4] = { pk2(a0.x, a0.y), pk2(a0.z, a0.w),
                                         pk2(a1.x, a1.y), pk2(a1.z, a1.w) };
            unsigned long long bd[8] = { pk2(b0.x, b0.x), pk2(b0.y, b0.y),
                                         pk2(b0.z, b0.z), pk2(b0.w, b0.w),
                                         pk2(b1.x, b1.x), pk2(b1.y, b1.y),
                                         pk2(b1.z, b1.z), pk2(b1.w, b1.w) };
            #pragma unroll
            for (int i = 0; i < 4; i++)
                #pragma unroll
                for (int j = 0; j < 8; j++)
                    fma2(acc[i][j], ap[i], bd[j]);
        }
        __syncthreads();
    }
    float bv[8];
    #pragma unroll
    for (int j = 0; j < 8; j++) bv[j] = bias[tc * 8 + j];
    #pragma unroll
    for (int i2 = 0; i2 < 4; i2++) {
        float2 v[8];
        #pragma unroll
        for (int j = 0; j < 8; j++) v[j] = upk2(acc[i2][j]);
        int r0 = row0 + tr * 8 + i2 * 2;
        if (r0 < nrows) {
            float4 o0 = make_float4(v[0].x + bv[0], v[1].x + bv[1],
                                    v[2].x + bv[2], v[3].x + bv[3]);
            float4 o1 = make_float4(v[4].x + bv[4], v[5].x + bv[5],
                                    v[6].x + bv[6], v[7].x + bv[7]);
            *(float4*)(g_hw + (size_t)r0 * HID + tc * 8)     = o0;
            *(float4*)(g_hw + (size_t)r0 * HID + tc * 8 + 4) = o1;
        }
        if (r0 + 1 < nrows) {
            float4 o0 = make_float4(v[0].y + bv[0], v[1].y + bv[1],
                                    v[2].y + bv[2], v[3].y + bv[3]);
            float4 o1 = make_float4(v[4].y + bv[4], v[5].y + bv[5],
                                    v[6].y + bv[6], v[7].y + bv[7]);
            *(float4*)(g_hw + (size_t)(r0 + 1) * HID + tc * 8)     = o0;
            *(float4*)(g_hw + (size_t)(r0 + 1) * HID + tc * 8 + 4) = o1;
        }
    }
}

// ---------------- aggregation (warp per node) + BN stats ----------------
__global__ __launch_bounds__(256) void agg_kernel() {
    __shared__ float bsum[HID];
    __shared__ float bss[HID];
    int tid = threadIdx.x;
    for (int i = tid; i < HID; i += blockDim.x) { bsum[i] = 0.f; bss[i] = 0.f; }
    __syncthreads();

    int lane = tid & 31;
    int wglobal = (blockIdx.x * blockDim.x + tid) >> 5;
    int nwarps  = (gridDim.x * blockDim.x) >> 5;

    float ls0 = 0.f, ls1 = 0.f, ls2 = 0.f, ls3 = 0.f;
    float lq0 = 0.f, lq1 = 0.f, lq2 = 0.f, lq3 = 0.f;

    for (int n = wglobal; n < NODES; n += nwarps) {
        float dv = g_dinv[n];
        float sn = dv * dv;
        float4 a = ((const float4*)(g_hw + (size_t)n * HID))[lane];
        float4 acc = make_float4(a.x * sn, a.y * sn, a.z * sn, a.w * sn);
        int beg = g_off[n], end = g_off[n + 1];
        int i = beg;
        for (; i + 2 <= end; i += 2) {
            int s0 = g_csr_src[i], s1 = g_csr_src[i + 1];
            float w0 = g_csr_norm[i], w1 = g_csr_norm[i + 1];
            float4 v0 = ((const float4*)(g_hw + (size_t)s0 * HID))[lane];
            float4 v1 = ((const float4*)(g_hw + (size_t)s1 * HID))[lane];
            acc.x += w0 * v0.x + w1 * v1.x;
            acc.y += w0 * v0.y + w1 * v1.y;
            acc.z += w0 * v0.z + w1 * v1.z;
            acc.w += w0 * v0.w + w1 * v1.w;
        }
        if (i < end) {
            int s  = g_csr_src[i];
            float w = g_csr_norm[i];
            float4 v = ((const float4*)(g_hw + (size_t)s * HID))[lane];
            acc.x += w * v.x; acc.y += w * v.y;
            acc.z += w * v.z; acc.w += w * v.w;
        }
        ((float4*)(g_agg + (size_t)n * HID))[lane] = acc;
        ls0 += acc.x; ls1 += acc.y; ls2 += acc.z; ls3 += acc.w;
        lq0 += acc.x * acc.x; lq1 += acc.y * acc.y;
        lq2 += acc.z * acc.z; lq3 += acc.w * acc.w;
    }
    int c = lane * 4;
    atomicAdd(&bsum[c + 0], ls0); atomicAdd(&bsum[c + 1], ls1);
    atomicAdd(&bsum[c + 2], ls2); atomicAdd(&bsum[c + 3], ls3);
    atomicAdd(&bss[c + 0], lq0);  atomicAdd(&bss[c + 1], lq1);
    atomicAdd(&bss[c + 2], lq2);  atomicAdd(&bss[c + 3], lq3);
    __syncthreads();
    for (int i = tid; i < HID; i += blockDim.x) {
        atomicAdd(&g_stats[i],       bsum[i]);
        atomicAdd(&g_stats[HID + i], bss[i]);
    }
}

// reads stats -> mean/scale, then re-zeroes stats for the next layer
__global__ void finalize_stats_kernel() {
    int j = threadIdx.x;   // 128
    float m = g_stats[j] * (1.0f / NODES);
    float v = g_stats[HID + j] * (1.0f / NODES) - m * m;
    g_mean[j]  = m;
    g_scale[j] = rsqrtf(v + BN_EPS);
    g_stats[j] = 0.f;
    g_stats[HID + j] = 0.f;
}

// only needed for the final layer (h is an output)
__global__ void bn_relu_kernel(float* __restrict__ h) {
    int idx = blockIdx.x * blockDim.x + threadIdx.x;   // float4 index
    if (idx >= NODES * 32) return;
    int c = (idx & 31) * 4;
    float4 v = ((const float4*)g_agg)[idx];
    float4 r;
    r.x = fmaxf((v.x - g_mean[c + 0]) * g_scale[c + 0], 0.f);
    r.y = fmaxf((v.y - g_mean[c + 1]) * g_scale[c + 1], 0.f);
    r.z = fmaxf((v.z - g_mean[c + 2]) * g_scale[c + 2], 0.f);
    r.w = fmaxf((v.w - g_mean[c + 3]) * g_scale[c + 3], 0.f);
    ((float4*)h)[idx] = r;
}

// ---------------- scoring prep ----------------
__global__ void prep_kernel(const float* __restrict__ h,
                            const float* __restrict__ l1w,
                            const float* __restrict__ l1b,
                            const int* __restrict__ curr) {
    int j = threadIdx.x;   // 128
    int c = *curr;
    float acc = 0.f;
    #pragma unroll 8
    for (int k = 0; k < HID; k++)
        acc += h[(size_t)c * HID + k] * l1w[(size_t)(HID + k) * HID + j];
    g_base[j] = l1b[j] + acc;
    float we = 0.f;
    #pragma unroll 8
    for (int k = 2 * HID; k < 4 * HID; k++)
        we += l1w[(size_t)k * HID + j];
    g_we[j] = we;
}

// ---------------- scoring GEMM + relu.w2 dot + partition pooling ----------------
__global__ __launch_bounds__(256) void score_kernel(
    const float* __restrict__ A,    // h
    const float* __restrict__ W,    // lin1_w rows 0..127
    const float* __restrict__ l2w, const float* __restrict__ l2b,
    const float* __restrict__ ecn, const float* __restrict__ parts,
    float* __restrict__ out)
{
    __shared__ float As[32 * 132];
    __shared__ float Bs[32 * 128];
    __shared__ float sarr[128];
    __shared__ float pp[NPART];
    int tid = threadIdx.x;
    int tr = tid >> 4, tc = tid & 15;
    int row0 = blockIdx.x * 128;
    unsigned long long acc[4][8];
    #pragma unroll
    for (int i = 0; i < 4; i++)
        #pragma unroll
        for (int j = 0; j < 8; j++) acc[i][j] = 0ull;

    for (int kc = 0; kc < HID; kc += 32) {
        #pragma unroll
        for (int i = 0; i < 4; i++) {
            int slot = tid + i * 256;
            int r  = slot >> 3;
            int k4 = slot & 7;
            float4 v = make_float4(0.f, 0.f, 0.f, 0.f);
            if (row0 + r < NODES)
                v = *(const float4*)(A + (size_t)(row0 + r) * HID + kc + k4 * 4);
            As[(k4 * 4 + 0) * 132 + r] = v.x;
            As[(k4 * 4 + 1) * 132 + r] = v.y;
            As[(k4 * 4 + 2) * 132 + r] = v.z;
            As[(k4 * 4 + 3) * 132 + r] = v.w;
        }
        #pragma unroll
        for (int i = 0; i < 4; i++) {
            int slot = tid + i * 256;
            int k  = slot >> 5;
            int c4 = slot & 31;
            *(float4*)(Bs + k * 128 + c4 * 4) =
                *(const float4*)(W + (size_t)(kc + k) * HID + c4 * 4);
        }
        __syncthreads();
        #pragma unroll
        for (int k = 0; k < 32; k++) {
            float4 a0 = *(float4*)(As + k * 132 + tr * 8);
            float4 a1 = *(float4*)(As + k * 132 + tr * 8 + 4);
            float4 b0 = *(float4*)(Bs + k * 128 + tc * 8);
            float4 b1 = *(float4*)(Bs + k * 128 + tc * 8 + 4);
            unsigned long long ap[4] = { pk2(a0.x, a0.y), pk2(a0.z, a0.w),
                                         pk2(a1.x, a1.y), pk2(a1.z, a1.w) };
            unsigned long long bd[8] = { pk2(b0.x, b0.x), pk2(b0.y, b0.y),
                                         pk2(b0.z, b0.z), pk2(b0.w, b0.w),
                                         pk2(b1.x, b1.x), pk2(b1.y, b1.y),
                                         pk2(b1.z, b1.z), pk2(b1.w, b1.w) };
            #pragma unroll
            for (int i = 0; i < 4; i++)
                #pragma unroll
                for (int j = 0; j < 8; j++)
                    fma2(acc[i][j], ap[i], bd[j]);
        }
        __syncthreads();
    }

    float w2[8], bb[8], wev[8];
    #pragma unroll
    for (int j = 0; j < 8; j++) {
        w2[j]  = l2w[tc * 8 + j];
        bb[j]  = g_base[tc * 8 + j];
        wev[j] = g_we[tc * 8 + j];
    }
    float b2 = l2b[0];
    #pragma unroll
    for (int i2 = 0; i2 < 4; i2++) {
        float2 v[8];
        #pragma unroll
        for (int j = 0; j < 8; j++) v[j] = upk2(acc[i2][j]);
        #pragma unroll
        for (int half = 0; half < 2; half++) {
            int row = row0 + tr * 8 + i2 * 2 + half;
            float e = (row < NODES) ? ecn[row] : 0.f;
            float s = 0.f;
            #pragma unroll
            for (int j = 0; j < 8; j++) {
                float val = half ? v[j].y : v[j].x;
                float t = val + bb[j] + e * wev[j];
                s += fmaxf(t, 0.f) * w2[j];
            }
            s += __shfl_xor_sync(0xffffffffu, s, 8, 16);
            s += __shfl_xor_sync(0xffffffffu, s, 4, 16);
            s += __shfl_xor_sync(0xffffffffu, s, 2, 16);
            s += __shfl_xor_sync(0xffffffffu, s, 1, 16);
            if (tc == 0) sarr[tr * 8 + i2 * 2 + half] = (row < NODES) ? (s + b2) : 0.f;
        }
    }
    if (tid < NPART) pp[tid] = 0.f;
    __syncthreads();
    int p = tid & 31, g = tid >> 5;
    float psum = 0.f;
    for (int r = g * 16; r < g * 16 + 16; r++) {
        int row = row0 + r;
        if (row < NODES) psum += sarr[r] * parts[(size_t)row * NPART + p];
    }
    atomicAdd(&pp[p], psum);
    __syncthreads();
    if (tid < NPART) atomicAdd(&out[tid], pp[tid]);
}

// ---------------- launcher ----------------
extern "C" void kernel_launch(void* const* d_in, const int* in_sizes, int n_in,
                              void* d_out, int out_size) {
    const float* x      = (const float*)d_in[0];
    const int*   ei     = (const int*)d_in[1];
    const float* ew     = (const float*)d_in[2];
    const float* parts  = (const float*)d_in[3];
    // d_in[4] = node_weights (unused by reference)
    const float* ecn    = (const float*)d_in[5];
    const float* conv_w = (const float*)d_in[6];
    const float* conv_b = (const float*)d_in[7];
    const float* l1w    = (const float*)d_in[8];
    const float* l1b    = (const float*)d_in[9];
    const float* l2w    = (const float*)d_in[10];
    const float* l2b    = (const float*)d_in[11];
    const int*   curr   = (const int*)d_in[12];

    float* out = (float*)d_out;          // [0:32) partition scores
    float* h   = out + NPART;            // [32 : 32+N*H) final h

    zero_init_kernel<<<(NODES + 255) / 256, 256>>>(out);
    deg_count_kernel<<<(NE + 255) / 256, 256>>>(ei, ew);
    block_sum_kernel<<<NSB, SBLK>>>();
    scan_bsum_kernel<<<1, 128>>>();
    scan_local_kernel<<<NSB, SBLK>>>();
    csr_fill_kernel<<<(NE + 255) / 256, 256>>>(ei, ew);

    const int gemm_blocks = (NODES + 127) / 128;   // 391
    // layer 0: plain x
    gemm_kernel<<<gemm_blocks, 256>>>(x, conv_w, conv_b, 0, NODES);
    agg_kernel<<<1184, 256>>>();
    finalize_stats_kernel<<<1, 128>>>();
    // layers 1..2: BN+ReLU fused into the GEMM A-load, reading g_agg (device-side)
    for (int l = 1; l < 3; l++) {
        gemm_kernel<<<gemm_blocks, 256>>>(nullptr, conv_w + (size_t)l * HID * HID,
                                          conv_b + (size_t)l * HID, 1, NODES);
        agg_kernel<<<1184, 256>>>();
        finalize_stats_kernel<<<1, 128>>>();
    }
    // final activation -> h (needed as output and for scoring)
    bn_relu_kernel<<<(NODES * 32 + 255) / 256, 256>>>(h);

    prep_kernel<<<1, 128>>>(h, l1w, l1b, curr);
    score_kernel<<<gemm_blocks, 256>>>(h, l1w, l2w, l2b, ecn, parts, out);
}